// round 6
// baseline (speedup 1.0000x reference)
#include <cuda_runtime.h>
#include <math.h>
#include <stdint.h>

// ---------------- problem constants ----------------
#define DM    1024
#define SEQ   1024
#define BATCH 8
#define RK    128
#define NC    64
#define NQK   32
#define NV    32
#define KC    8
#define KQK   4
#define KV    6
#define NHEAD 16
#define DH    64
#define NW    128

// ---------------- device scratch ----------------
__device__ float g_prefw[BATCH * SEQ * NW];
__device__ float g_part[BATCH * 16 * NW];
__device__ int   g_cidx[BATCH * KC];
__device__ float g_cval[BATCH * KC];
__device__ int   g_qidx[BATCH * KQK];
__device__ float g_qval[BATCH * KQK];
__device__ int   g_vidx[BATCH * KV];
__device__ float g_vval[BATCH * KV];
__device__ float g_sc [BATCH * DM * RK];
__device__ float g_eqk[BATCH * RK * DM];
__device__ float g_ev [BATCH * RK * DM];
__device__ float g_h  [BATCH * SEQ * RK];
__device__ float g_Q  [BATCH * SEQ * DM];
__device__ float g_V  [BATCH * SEQ * DM];
__device__ float g_ao [BATCH * SEQ * DM];

// ---------------- tf32 helpers ----------------
__device__ __forceinline__ uint32_t f2tf(float x) {
    uint32_t r;
    asm("cvt.rna.tf32.f32 %0, %1;" : "=r"(r) : "f"(x));
    return r;
}
__device__ __forceinline__ void mma_tf32(float4& d, const uint32_t a[4], const uint32_t b[2]) {
    asm volatile(
        "mma.sync.aligned.m16n8k8.row.col.f32.tf32.tf32.f32 "
        "{%0,%1,%2,%3}, {%4,%5,%6,%7}, {%8,%9}, {%0,%1,%2,%3};\n"
        : "+f"(d.x), "+f"(d.y), "+f"(d.z), "+f"(d.w)
        : "r"(a[0]), "r"(a[1]), "r"(a[2]), "r"(a[3]), "r"(b[0]), "r"(b[1]));
}

// =====================================================================
// Router GEMM (fp32, BM=64 for 128-block coverage): logits = x @ W^T,
// fused 3-group softmax * importance epilogue.
// =====================================================================
__global__ __launch_bounds__(256, 2) void router_gemm(
    const float* __restrict__ x,  const float* __restrict__ Wc,
    const float* __restrict__ Wqk, const float* __restrict__ Wv,
    const float* __restrict__ imp)
{
    __shared__ float As[16][68];
    __shared__ float Bs[16][132];
    int tid = threadIdx.x, tx = tid & 15, ty = tid >> 4;
    int m0 = blockIdx.y * 64;
    float acc[4][8] = {};
    const int nkb = DM / 16;
    float4 pa, pb[2];

    auto LD = [&](int kb) {
        {
            int r = tid >> 2, q = tid & 3;
            pa = *(const float4*)&x[(size_t)(m0 + r) * DM + kb * 16 + q * 4];
        }
#pragma unroll
        for (int i = 0; i < 2; i++) {
            int f = tid + i * 256; int n = f >> 2, q = f & 3;
            const float* wrow = (n < NC) ? (Wc + (size_t)n * DM)
                              : (n < NC + NQK) ? (Wqk + (size_t)(n - NC) * DM)
                              : (Wv + (size_t)(n - NC - NQK) * DM);
            pb[i] = *(const float4*)&wrow[kb * 16 + q * 4];
        }
    };
    auto ST = [&]() {
        {
            int r = tid >> 2, q = tid & 3;
            As[q*4+0][r] = pa.x; As[q*4+1][r] = pa.y;
            As[q*4+2][r] = pa.z; As[q*4+3][r] = pa.w;
        }
#pragma unroll
        for (int i = 0; i < 2; i++) {
            int f = tid + i * 256; int n = f >> 2, q = f & 3;
            Bs[q*4+0][n] = pb[i].x; Bs[q*4+1][n] = pb[i].y;
            Bs[q*4+2][n] = pb[i].z; Bs[q*4+3][n] = pb[i].w;
        }
    };

    LD(0); ST(); __syncthreads();
    for (int kb = 0; kb < nkb; kb++) {
        bool more = (kb + 1 < nkb);
        if (more) LD(kb + 1);
#pragma unroll
        for (int k = 0; k < 16; k++) {
            float a[4], b[8];
            *(float4*)&a[0] = *(const float4*)&As[k][ty * 4];
            *(float4*)&b[0] = *(const float4*)&Bs[k][tx * 4];
            *(float4*)&b[4] = *(const float4*)&Bs[k][64 + tx * 4];
#pragma unroll
            for (int i = 0; i < 4; i++)
#pragma unroll
                for (int j = 0; j < 8; j++)
                    acc[i][j] = fmaf(a[i], b[j], acc[i][j]);
        }
        __syncthreads();
        if (more) { ST(); __syncthreads(); }
    }

#pragma unroll
    for (int i = 0; i < 4; i++) {
        int bs = m0 + ty * 4 + i;
        float mC = fmaxf(fmaxf(acc[i][0], acc[i][1]), fmaxf(acc[i][2], acc[i][3]));
#pragma unroll
        for (int w = 1; w < 16; w <<= 1) mC = fmaxf(mC, __shfl_xor_sync(0xffffffffu, mC, w));
        float e0 = __expf(acc[i][0] - mC), e1 = __expf(acc[i][1] - mC);
        float e2 = __expf(acc[i][2] - mC), e3 = __expf(acc[i][3] - mC);
        float sC = e0 + e1 + e2 + e3;
#pragma unroll
        for (int w = 1; w < 16; w <<= 1) sC += __shfl_xor_sync(0xffffffffu, sC, w);

        float m2 = fmaxf(fmaxf(acc[i][4], acc[i][5]), fmaxf(acc[i][6], acc[i][7]));
#pragma unroll
        for (int w = 1; w < 8; w <<= 1) m2 = fmaxf(m2, __shfl_xor_sync(0xffffffffu, m2, w));
        float f0 = __expf(acc[i][4] - m2), f1 = __expf(acc[i][5] - m2);
        float f2 = __expf(acc[i][6] - m2), f3 = __expf(acc[i][7] - m2);
        float s2 = f0 + f1 + f2 + f3;
#pragma unroll
        for (int w = 1; w < 8; w <<= 1) s2 += __shfl_xor_sync(0xffffffffu, s2, w);

        float ip = imp[bs];
        float iC = ip / sC, i2 = ip / s2;
        float4 o0 = {e0 * iC, e1 * iC, e2 * iC, e3 * iC};
        float4 o1 = {f0 * i2, f1 * i2, f2 * i2, f3 * i2};
        *(float4*)&g_prefw[(size_t)bs * NW + tx * 4]      = o0;
        *(float4*)&g_prefw[(size_t)bs * NW + 64 + tx * 4] = o1;
    }
}

// ---------------- stage-1 reduction over S ----------------
__global__ void reduce1_kernel() {
    int b = blockIdx.x, chunk = blockIdx.y, t = threadIdx.x;
    const float* p = g_prefw + ((size_t)b * SEQ + chunk * 64) * NW + t;
    float s = 0.f;
#pragma unroll 8
    for (int i = 0; i < 64; i++) s += p[(size_t)i * NW];
    g_part[(b * 16 + chunk) * NW + t] = s;
}

// ---------------- fused stage-2 reduction + top-k + renormalize ----------------
__device__ void topk_store(const float* v, int n, int k, int* oidx, float* oval) {
    float tmp[64];
    for (int i = 0; i < n; i++) tmp[i] = v[i];
    float sum = 0.f;
    for (int j = 0; j < k; j++) {
        int bi = 0; float bv = tmp[0];
        for (int i = 1; i < n; i++) { if (tmp[i] > bv) { bv = tmp[i]; bi = i; } }
        oidx[j] = bi; oval[j] = bv; sum += bv;
        tmp[bi] = -1e30f;
    }
    float inv = 1.f / (sum + 1e-8f);
    for (int j = 0; j < k; j++) oval[j] *= inv;
}
__global__ void reduce2_topk_kernel() {
    __shared__ float acc[NW];
    int b = blockIdx.x, t = threadIdx.x;
    float s = 0.f;
#pragma unroll
    for (int c = 0; c < 16; c++) s += g_part[(b * 16 + c) * NW + t];
    acc[t] = s;
    __syncthreads();
    if (t == 0)      topk_store(acc,            NC,  KC,  g_cidx + b * KC,  g_cval + b * KC);
    else if (t == 1) topk_store(acc + NC,       NQK, KQK, g_qidx + b * KQK, g_qval + b * KQK);
    else if (t == 2) topk_store(acc + NC + NQK, NV,  KV,  g_vidx + b * KV,  g_vval + b * KV);
}

// ---------------- merged sparse weighted mixes (one kernel) ----------------
__global__ void build_mix_kernel(const float* __restrict__ CN,
                                 const float* __restrict__ EQK,
                                 const float* __restrict__ EV) {
    const int SZ = DM * RK;
    int b = blockIdx.y;
    int i = blockIdx.x * blockDim.x + threadIdx.x;   // 0 .. 3*SZ-1
    if (i < SZ) {
        float s = 0.f;
#pragma unroll
        for (int j = 0; j < KC; j++) {
            int n = g_cidx[b * KC + j];
            s = fmaf(g_cval[b * KC + j], CN[(size_t)n * SZ + i], s);
        }
        g_sc[(size_t)b * SZ + i] = s;
    } else if (i < 2 * SZ) {
        int p = i - SZ;
        float s = 0.f;
#pragma unroll
        for (int j = 0; j < KQK; j++) {
            int n = g_qidx[b * KQK + j];
            s = fmaf(g_qval[b * KQK + j], EQK[(size_t)n * SZ + p], s);
        }
        g_eqk[(size_t)b * SZ + p] = s;
    } else {
        int p = i - 2 * SZ;
        float s = 0.f;
#pragma unroll
        for (int j = 0; j < KV; j++) {
            int n = g_vidx[b * KV + j];
            s = fmaf(g_vval[b * KV + j], EV[(size_t)n * SZ + p], s);
        }
        g_ev[(size_t)b * SZ + p] = s;
    }
}

// =====================================================================
// tf32 GEMM (nn), double-buffered smem, single sync per k-iter.
// BM=BN=128, BK=16, 8 warps (4m x 2n).
// =====================================================================
__global__ __launch_bounds__(256, 2) void gemm_nn_mma(
    const float* __restrict__ A, const float* __restrict__ B,
    float* __restrict__ C, int N, int K,
    long long sA, long long sB, long long sC)
{
    __shared__ uint32_t As[2][128 * 20];
    __shared__ uint32_t Bs[2][16 * 136];
    A += (long long)blockIdx.z * sA;
    B += (long long)blockIdx.z * sB;
    C += (long long)blockIdx.z * sC;
    int tid = threadIdx.x, lane = tid & 31, w = tid >> 5;
    int gq = lane >> 2, qd = lane & 3;
    int wm = w & 3, wn = w >> 2;
    int m0 = blockIdx.y * 128, n0 = blockIdx.x * 128;

    float4 acc[2][8];
#pragma unroll
    for (int i = 0; i < 2; i++)
#pragma unroll
        for (int j = 0; j < 8; j++) acc[i][j] = make_float4(0.f, 0.f, 0.f, 0.f);

    const int nkb = K / 16;
    float4 pa[2], pb[2];

    auto LD = [&](int kb) {
#pragma unroll
        for (int i = 0; i < 2; i++) {
            int f = tid + i * 256; int r = f >> 2, q = f & 3;
            pa[i] = *(const float4*)&A[(size_t)(m0 + r) * K + kb * 16 + q * 4];
        }
#pragma unroll
        for (int i = 0; i < 2; i++) {
            int f = tid + i * 256; int r = f >> 5, c = f & 31;
            pb[i] = *(const float4*)&B[(size_t)(kb * 16 + r) * N + n0 + c * 4];
        }
    };
    auto ST = [&](int buf) {
#pragma unroll
        for (int i = 0; i < 2; i++) {
            int f = tid + i * 256; int r = f >> 2, q = f & 3;
            uint32_t* da = &As[buf][r * 20 + q * 4];
            da[0] = f2tf(pa[i].x); da[1] = f2tf(pa[i].y);
            da[2] = f2tf(pa[i].z); da[3] = f2tf(pa[i].w);
        }
#pragma unroll
        for (int i = 0; i < 2; i++) {
            int f = tid + i * 256; int r = f >> 5, c = f & 31;
            uint32_t* db = &Bs[buf][r * 136 + c * 4];
            db[0] = f2tf(pb[i].x); db[1] = f2tf(pb[i].y);
            db[2] = f2tf(pb[i].z); db[3] = f2tf(pb[i].w);
        }
    };

    LD(0); ST(0); __syncthreads();
    for (int kb = 0; kb < nkb; kb++) {
        bool more = (kb + 1 < nkb);
        if (more) LD(kb + 1);
        int cur = kb & 1;
#pragma unroll
        for (int s = 0; s < 2; s++) {
            int kbs = s * 8;
            uint32_t af[2][4];
#pragma unroll
            for (int i = 0; i < 2; i++) {
                int r = wm * 32 + i * 16 + gq;
                af[i][0] = As[cur][r * 20 + kbs + qd];
                af[i][1] = As[cur][(r + 8) * 20 + kbs + qd];
                af[i][2] = As[cur][r * 20 + kbs + qd + 4];
                af[i][3] = As[cur][(r + 8) * 20 + kbs + qd + 4];
            }
            uint32_t bf[8][2];
#pragma unroll
            for (int j = 0; j < 8; j++) {
                int n = wn * 64 + j * 8 + gq;
                bf[j][0] = Bs[cur][(kbs + qd) * 136 + n];
                bf[j][1] = Bs[cur][(kbs + qd + 4) * 136 + n];
            }
#pragma unroll
            for (int i = 0; i < 2; i++)
#pragma unroll
                for (int j = 0; j < 8; j++)
                    mma_tf32(acc[i][j], af[i], bf[j]);
        }
        if (more) { ST(cur ^ 1); __syncthreads(); }
    }

#pragma unroll
    for (int i = 0; i < 2; i++) {
        int r0 = m0 + wm * 32 + i * 16 + gq;
#pragma unroll
        for (int j = 0; j < 8; j++) {
            int c0 = n0 + wn * 64 + j * 8 + 2 * qd;
            *(float2*)&C[(size_t)r0 * N + c0]       = make_float2(acc[i][j].x, acc[i][j].y);
            *(float2*)&C[(size_t)(r0 + 8) * N + c0] = make_float2(acc[i][j].z, acc[i][j].w);
        }
    }
}

// =====================================================================
// Out-projection (nt), double-buffered smem, single sync per k-iter.
// =====================================================================
__global__ __launch_bounds__(256, 2) void gemm_nt_mma(
    const float* __restrict__ A, const float* __restrict__ B,
    float* __restrict__ C, int N, int K)
{
    __shared__ uint32_t As[2][128 * 20];
    __shared__ uint32_t Bs[2][128 * 20];
    int tid = threadIdx.x, lane = tid & 31, w = tid >> 5;
    int gq = lane >> 2, qd = lane & 3;
    int wm = w & 3, wn = w >> 2;
    int m0 = blockIdx.y * 128, n0 = blockIdx.x * 128;

    float4 acc[2][8];
#pragma unroll
    for (int i = 0; i < 2; i++)
#pragma unroll
        for (int j = 0; j < 8; j++) acc[i][j] = make_float4(0.f, 0.f, 0.f, 0.f);

    const int nkb = K / 16;
    float4 pa[2], pb[2];

    auto LD = [&](int kb) {
#pragma unroll
        for (int i = 0; i < 2; i++) {
            int f = tid + i * 256; int r = f >> 2, q = f & 3;
            pa[i] = *(const float4*)&A[(size_t)(m0 + r) * K + kb * 16 + q * 4];
            pb[i] = *(const float4*)&B[(size_t)(n0 + r) * K + kb * 16 + q * 4];
        }
    };
    auto ST = [&](int buf) {
#pragma unroll
        for (int i = 0; i < 2; i++) {
            int f = tid + i * 256; int r = f >> 2, q = f & 3;
            uint32_t* da = &As[buf][r * 20 + q * 4];
            da[0] = f2tf(pa[i].x); da[1] = f2tf(pa[i].y);
            da[2] = f2tf(pa[i].z); da[3] = f2tf(pa[i].w);
            uint32_t* db = &Bs[buf][r * 20 + q * 4];
            db[0] = f2tf(pb[i].x); db[1] = f2tf(pb[i].y);
            db[2] = f2tf(pb[i].z); db[3] = f2tf(pb[i].w);
        }
    };

    LD(0); ST(0); __syncthreads();
    for (int kb = 0; kb < nkb; kb++) {
        bool more = (kb + 1 < nkb);
        if (more) LD(kb + 1);
        int cur = kb & 1;
#pragma unroll
        for (int s = 0; s < 2; s++) {
            int kbs = s * 8;
            uint32_t af[2][4];
#pragma unroll
            for (int i = 0; i < 2; i++) {
                int r = wm * 32 + i * 16 + gq;
                af[i][0] = As[cur][r * 20 + kbs + qd];
                af[i][1] = As[cur][(r + 8) * 20 + kbs + qd];
                af[i][2] = As[cur][r * 20 + kbs + qd + 4];
                af[i][3] = As[cur][(r + 8) * 20 + kbs + qd + 4];
            }
            uint32_t bf[8][2];
#pragma unroll
            for (int j = 0; j < 8; j++) {
                int n = wn * 64 + j * 8 + gq;
                bf[j][0] = Bs[cur][n * 20 + kbs + qd];
                bf[j][1] = Bs[cur][n * 20 + kbs + qd + 4];
            }
#pragma unroll
            for (int i = 0; i < 2; i++)
#pragma unroll
                for (int j = 0; j < 8; j++)
                    mma_tf32(acc[i][j], af[i], bf[j]);
        }
        if (more) { ST(cur ^ 1); __syncthreads(); }
    }

#pragma unroll
    for (int i = 0; i < 2; i++) {
        int r0 = m0 + wm * 32 + i * 16 + gq;
#pragma unroll
        for (int j = 0; j < 8; j++) {
            int c0 = n0 + wn * 64 + j * 8 + 2 * qd;
            *(float2*)&C[(size_t)r0 * N + c0]       = make_float2(acc[i][j].x, acc[i][j].y);
            *(float2*)&C[(size_t)(r0 + 8) * N + c0] = make_float2(acc[i][j].z, acc[i][j].w);
        }
    }
}

// =====================================================================
// Flash attention (K==Q), causal, tf32 mma. 128-row q-tiles, 8 warps.
// Warp w owns rows 16w..16w+15. P lives in per-warp rows of Qs ->
// only __syncwarp between P store and PV; one __syncthreads per kv tile.
// =====================================================================
__global__ __launch_bounds__(256) void flash_mma() {
    extern __shared__ uint32_t sm[];
    uint32_t* Qs = sm;                  // 128 x 68 (Q staging, then P)
    uint32_t* Ks = sm + 128 * 68;       // 64 x 68
    uint32_t* Vs = sm + 128 * 68 + 64 * 68;  // 64 x 72

    int qt = gridDim.x - 1 - blockIdx.x;    // heavy tiles first
    int h = blockIdx.y, b = blockIdx.z;
    int tid = threadIdx.x, lane = tid & 31, w = tid >> 5;
    int gq = lane >> 2, qd = lane & 3;

    const float* Qb = g_Q + (size_t)b * SEQ * DM + (size_t)h * DH;
    const float* Vb = g_V + (size_t)b * SEQ * DM + (size_t)h * DH;

    // stage Q tile (128 rows), tf32
    for (int f = tid; f < 128 * 16; f += 256) {
        int r = f >> 4, q = f & 15;
        float4 v = *(const float4*)&Qb[(size_t)(qt * 128 + r) * DM + q * 4];
        uint32_t* d = &Qs[r * 68 + q * 4];
        d[0] = f2tf(v.x); d[1] = f2tf(v.y); d[2] = f2tf(v.z); d[3] = f2tf(v.w);
    }
    __syncthreads();

    // register-resident Q fragments (own rows)
    uint32_t qa[8][4];
    int qr = w * 16 + gq;
#pragma unroll
    for (int ka = 0; ka < 8; ka++) {
        qa[ka][0] = Qs[qr * 68 + ka * 8 + qd];
        qa[ka][1] = Qs[(qr + 8) * 68 + ka * 8 + qd];
        qa[ka][2] = Qs[qr * 68 + ka * 8 + qd + 4];
        qa[ka][3] = Qs[(qr + 8) * 68 + ka * 8 + qd + 4];
    }

    float mr0 = -1e30f, mr1 = -1e30f, lr0 = 0.f, lr1 = 0.f;
    float4 oacc[8];
#pragma unroll
    for (int j = 0; j < 8; j++) oacc[j] = make_float4(0.f, 0.f, 0.f, 0.f);

    int row0 = qt * 128 + w * 16 + gq;
    int row1 = row0 + 8;
    const float scale = 0.125f;
    const int nkt = 2 * qt + 2;   // 64-col kv tiles covering cols [0, 128(qt+1))

    for (int kt = 0; kt < nkt; kt++) {
        __syncthreads();   // all warps done with prior Ks/Vs (and Q frags on iter 0)
        for (int f = tid; f < 64 * 16; f += 256) {
            int r = f >> 4, q = f & 15;
            float4 kv = *(const float4*)&Qb[(size_t)(kt * 64 + r) * DM + q * 4];
            uint32_t* dk = &Ks[r * 68 + q * 4];
            dk[0] = f2tf(kv.x); dk[1] = f2tf(kv.y); dk[2] = f2tf(kv.z); dk[3] = f2tf(kv.w);
            float4 vv = *(const float4*)&Vb[(size_t)(kt * 64 + r) * DM + q * 4];
            uint32_t* dv = &Vs[r * 72 + q * 4];
            dv[0] = f2tf(vv.x); dv[1] = f2tf(vv.y); dv[2] = f2tf(vv.z); dv[3] = f2tf(vv.w);
        }
        __syncthreads();

        // S = Q @ K^T (each warp: 16x64)
        float4 sacc[8];
#pragma unroll
        for (int j = 0; j < 8; j++) sacc[j] = make_float4(0.f, 0.f, 0.f, 0.f);
#pragma unroll
        for (int ka = 0; ka < 8; ka++) {
#pragma unroll
            for (int j = 0; j < 8; j++) {
                uint32_t bb[2];
                bb[0] = Ks[(j * 8 + gq) * 68 + ka * 8 + qd];
                bb[1] = Ks[(j * 8 + gq) * 68 + ka * 8 + qd + 4];
                mma_tf32(sacc[j], qa[ka], bb);
            }
        }

        // scale + causal mask + online softmax
        bool needmask = (kt >= 2 * qt);   // kv tile reaches/overlaps diagonal block
        float p0[8], p1[8], p2[8], p3[8];
        float mx0 = -1e30f, mx1 = -1e30f;
#pragma unroll
        for (int j = 0; j < 8; j++) {
            int col = kt * 64 + j * 8 + 2 * qd;
            float c0 = sacc[j].x * scale, c1 = sacc[j].y * scale;
            float c2 = sacc[j].z * scale, c3 = sacc[j].w * scale;
            if (needmask) {
                if (col     > row0) c0 = -1e30f;
                if (col + 1 > row0) c1 = -1e30f;
                if (col     > row1) c2 = -1e30f;
                if (col + 1 > row1) c3 = -1e30f;
            }
            p0[j] = c0; p1[j] = c1; p2[j] = c2; p3[j] = c3;
            mx0 = fmaxf(mx0, fmaxf(c0, c1));
            mx1 = fmaxf(mx1, fmaxf(c2, c3));
        }
        mx0 = fmaxf(mx0, __shfl_xor_sync(0xffffffffu, mx0, 1));
        mx0 = fmaxf(mx0, __shfl_xor_sync(0xffffffffu, mx0, 2));
        mx1 = fmaxf(mx1, __shfl_xor_sync(0xffffffffu, mx1, 1));
        mx1 = fmaxf(mx1, __shfl_xor_sync(0xffffffffu, mx1, 2));

        float mn0 = fmaxf(mr0, mx0), mn1 = fmaxf(mr1, mx1);
        float al0 = __expf(mr0 - mn0), al1 = __expf(mr1 - mn1);
        float ps0 = 0.f, ps1 = 0.f;
#pragma unroll
        for (int j = 0; j < 8; j++) {
            p0[j] = __expf(p0[j] - mn0); p1[j] = __expf(p1[j] - mn0);
            p2[j] = __expf(p2[j] - mn1); p3[j] = __expf(p3[j] - mn1);
            ps0 += p0[j] + p1[j];
            ps1 += p2[j] + p3[j];
        }
        ps0 += __shfl_xor_sync(0xffffffffu, ps0, 1);
        ps0 += __shfl_xor_sync(0xffffffffu, ps0, 2);
        ps1 += __shfl_xor_sync(0xffffffffu, ps1, 1);
        ps1 += __shfl_xor_sync(0xffffffffu, ps1, 2);

        lr0 = lr0 * al0 + ps0; lr1 = lr1 * al1 + ps1;
        mr0 = mn0; mr1 = mn1;
#pragma unroll
        for (int j = 0; j < 8; j++) {
            oacc[j].x *= al0; oacc[j].y *= al0;
            oacc[j].z *= al1; oacc[j].w *= al1;
        }

        // P (tf32) into own rows of Qs; per-warp only -> __syncwarp suffices
        int pr0 = w * 16 + gq;
#pragma unroll
        for (int j = 0; j < 8; j++) {
            int cl = j * 8 + 2 * qd;
            Qs[pr0 * 68 + cl]           = f2tf(p0[j]);
            Qs[pr0 * 68 + cl + 1]       = f2tf(p1[j]);
            Qs[(pr0 + 8) * 68 + cl]     = f2tf(p2[j]);
            Qs[(pr0 + 8) * 68 + cl + 1] = f2tf(p3[j]);
        }
        __syncwarp();

        // O += P @ V
#pragma unroll
        for (int ka = 0; ka < 8; ka++) {
            uint32_t pa[4];
            pa[0] = Qs[pr0 * 68 + ka * 8 + qd];
            pa[1] = Qs[(pr0 + 8) * 68 + ka * 8 + qd];
            pa[2] = Qs[pr0 * 68 + ka * 8 + qd + 4];
            pa[3] = Qs[(pr0 + 8) * 68 + ka * 8 + qd + 4];
#pragma unroll
            for (int j = 0; j < 8; j++) {
                uint32_t vb[2];
                vb[0] = Vs[(ka * 8 + qd) * 72 + j * 8 + gq];
                vb[1] = Vs[(ka * 8 + qd + 4) * 72 + j * 8 + gq];
                mma_tf32(oacc[j], pa, vb);
            }
        }
    }

    float inv0 = 1.f / lr0, inv1 = 1.f / lr1;
    float* Ob = g_ao + ((size_t)b * SEQ + row0) * DM + (size_t)h * DH;
#pragma unroll
    for (int j = 0; j < 8; j++) {
        int c = j * 8 + 2 * qd;
        *(float2*)&Ob[c]            = make_float2(oacc[j].x * inv0, oacc[j].y * inv0);
        *(float2*)&Ob[8 * DM + c]   = make_float2(oacc[j].z * inv1, oacc[j].w * inv1);
    }
}

// ---------------- launch ----------------
extern "C" void kernel_launch(void* const* d_in, const int* in_sizes, int n_in,
                              void* d_out, int out_size) {
    const float* x   = (const float*)d_in[0];
    const float* imp = (const float*)d_in[1];
    const float* Wc  = (const float*)d_in[2];
    const float* Wqk = (const float*)d_in[3];
    const float* Wv  = (const float*)d_in[4];
    const float* CN  = (const float*)d_in[5];
    const float* EQK = (const float*)d_in[6];
    const float* EV  = (const float*)d_in[7];
    const float* Wo  = (const float*)d_in[8];
    float* out = (float*)d_out;

    float *p_sc, *p_eqk, *p_ev, *p_h, *p_Q, *p_V, *p_ao;
    cudaGetSymbolAddress((void**)&p_sc,  g_sc);
    cudaGetSymbolAddress((void**)&p_eqk, g_eqk);
    cudaGetSymbolAddress((void**)&p_ev,  g_ev);
    cudaGetSymbolAddress((void**)&p_h,   g_h);
    cudaGetSymbolAddress((void**)&p_Q,   g_Q);
    cudaGetSymbolAddress((void**)&p_V,   g_V);
    cudaGetSymbolAddress((void**)&p_ao,  g_ao);

    static int smem_set = 0;
    const int flash_smem = (128 * 68 + 64 * 68 + 64 * 72) * (int)sizeof(uint32_t); // 70656
    if (!smem_set) {
        cudaFuncSetAttribute(flash_mma,
                             cudaFuncAttributeMaxDynamicSharedMemorySize, flash_smem);
        smem_set = 1;
    }

    // 1) router GEMM + fused softmax*importance (128 blocks)
    router_gemm<<<dim3(1, (BATCH * SEQ) / 64), 256>>>(x, Wc, Wqk, Wv, imp);
    // 2) reduction over S + top-k (fused)
    reduce1_kernel<<<dim3(BATCH, 16), NW>>>();
    reduce2_topk_kernel<<<BATCH, NW>>>();
    // 3) merged sparse mixes
    build_mix_kernel<<<dim3(3 * (DM * RK) / 256, BATCH), 256>>>(CN, EQK, EV);
    // 4) h = x @ sc (tf32)
    gemm_nn_mma<<<dim3(1, SEQ / 128, BATCH), 256>>>(
        x, p_sc, p_h, RK, DM,
        (long long)SEQ * DM, (long long)DM * RK, (long long)SEQ * RK);
    // 5) Q = h @ eqk (tf32)
    gemm_nn_mma<<<dim3(DM / 128, SEQ / 128, BATCH), 256>>>(
        p_h, p_eqk, p_Q, DM, RK,
        (long long)SEQ * RK, (long long)RK * DM, (long long)SEQ * DM);
    // 6) V = h @ ev (tf32)
    gemm_nn_mma<<<dim3(DM / 128, SEQ / 128, BATCH), 256>>>(
        p_h, p_ev, p_V, DM, RK,
        (long long)SEQ * RK, (long long)RK * DM, (long long)SEQ * DM);
    // 7) flash attention (tf32 mma, 128-row q-tiles)
    flash_mma<<<dim3(SEQ / 128, NHEAD, BATCH), 256, flash_smem>>>();
    // 8) out = ao @ Wo^T (tf32 mma)
    gemm_nt_mma<<<dim3(DM / 128, (BATCH * SEQ) / 128), 256>>>(
        p_ao, Wo, out, DM, DM);
}

// round 7
// speedup vs baseline: 1.0720x; 1.0720x over previous
#include <cuda_runtime.h>
#include <math.h>
#include <stdint.h>

// ---------------- problem constants ----------------
#define DM    1024
#define SEQ   1024
#define BATCH 8
#define RK    128
#define NC    64
#define NQK   32
#define NV    32
#define KC    8
#define KQK   4
#define KV    6
#define NHEAD 16
#define DH    64
#define NW    128

// ---------------- device scratch ----------------
__device__ float g_prefw[BATCH * SEQ * NW];
__device__ float g_part[BATCH * 16 * NW];
__device__ int   g_cidx[BATCH * KC];
__device__ float g_cval[BATCH * KC];
__device__ int   g_qidx[BATCH * KQK];
__device__ float g_qval[BATCH * KQK];
__device__ int   g_vidx[BATCH * KV];
__device__ float g_vval[BATCH * KV];
__device__ float g_sc [BATCH * DM * RK];
__device__ float g_eqk[BATCH * RK * DM];
__device__ float g_ev [BATCH * RK * DM];
__device__ float g_h  [BATCH * SEQ * RK];
__device__ float g_Q  [BATCH * SEQ * DM];
__device__ float g_V  [BATCH * SEQ * DM];
__device__ float g_ao [BATCH * SEQ * DM];

// ---------------- tf32 helpers ----------------
__device__ __forceinline__ uint32_t f2tf(float x) {
    uint32_t r;
    asm("cvt.rna.tf32.f32 %0, %1;" : "=r"(r) : "f"(x));
    return r;
}
__device__ __forceinline__ void mma_tf32(float4& d, const uint32_t a[4], const uint32_t b[2]) {
    asm volatile(
        "mma.sync.aligned.m16n8k8.row.col.f32.tf32.tf32.f32 "
        "{%0,%1,%2,%3}, {%4,%5,%6,%7}, {%8,%9}, {%0,%1,%2,%3};\n"
        : "+f"(d.x), "+f"(d.y), "+f"(d.z), "+f"(d.w)
        : "r"(a[0]), "r"(a[1]), "r"(a[2]), "r"(a[3]), "r"(b[0]), "r"(b[1]));
}

// =====================================================================
// Router GEMM (fp32, BM=128 — round-5 known-good): logits = x @ W^T,
// fused 3-group softmax * importance epilogue.
// =====================================================================
__global__ __launch_bounds__(256, 2) void router_gemm(
    const float* __restrict__ x,  const float* __restrict__ Wc,
    const float* __restrict__ Wqk, const float* __restrict__ Wv,
    const float* __restrict__ imp)
{
    __shared__ float As[16][132];
    __shared__ float Bs[16][132];
    int tid = threadIdx.x, tx = tid & 15, ty = tid >> 4;
    int m0 = blockIdx.y * 128;
    float acc[8][8] = {};
    const int nkb = DM / 16;
    float4 pa[2], pb[2];

    auto LD = [&](int kb) {
#pragma unroll
        for (int i = 0; i < 2; i++) {
            int f = tid + i * 256; int r = f >> 2, q = f & 3;
            pa[i] = *(const float4*)&x[(size_t)(m0 + r) * DM + kb * 16 + q * 4];
        }
#pragma unroll
        for (int i = 0; i < 2; i++) {
            int f = tid + i * 256; int n = f >> 2, q = f & 3;
            const float* wrow = (n < NC) ? (Wc + (size_t)n * DM)
                              : (n < NC + NQK) ? (Wqk + (size_t)(n - NC) * DM)
                              : (Wv + (size_t)(n - NC - NQK) * DM);
            pb[i] = *(const float4*)&wrow[kb * 16 + q * 4];
        }
    };
    auto ST = [&]() {
#pragma unroll
        for (int i = 0; i < 2; i++) {
            int f = tid + i * 256; int r = f >> 2, q = f & 3;
            As[q*4+0][r] = pa[i].x; As[q*4+1][r] = pa[i].y;
            As[q*4+2][r] = pa[i].z; As[q*4+3][r] = pa[i].w;
        }
#pragma unroll
        for (int i = 0; i < 2; i++) {
            int f = tid + i * 256; int n = f >> 2, q = f & 3;
            Bs[q*4+0][n] = pb[i].x; Bs[q*4+1][n] = pb[i].y;
            Bs[q*4+2][n] = pb[i].z; Bs[q*4+3][n] = pb[i].w;
        }
    };

    LD(0); ST(); __syncthreads();
    for (int kb = 0; kb < nkb; kb++) {
        bool more = (kb + 1 < nkb);
        if (more) LD(kb + 1);
#pragma unroll
        for (int k = 0; k < 16; k++) {
            float a[8], b[8];
            *(float4*)&a[0] = *(const float4*)&As[k][ty * 4];
            *(float4*)&a[4] = *(const float4*)&As[k][64 + ty * 4];
            *(float4*)&b[0] = *(const float4*)&Bs[k][tx * 4];
            *(float4*)&b[4] = *(const float4*)&Bs[k][64 + tx * 4];
#pragma unroll
            for (int i = 0; i < 8; i++)
#pragma unroll
                for (int j = 0; j < 8; j++)
                    acc[i][j] = fmaf(a[i], b[j], acc[i][j]);
        }
        __syncthreads();
        if (more) { ST(); __syncthreads(); }
    }

#pragma unroll
    for (int i = 0; i < 8; i++) {
        int r = (i < 4) ? (ty * 4 + i) : (64 + ty * 4 + i - 4);
        int bs = m0 + r;
        float mC = fmaxf(fmaxf(acc[i][0], acc[i][1]), fmaxf(acc[i][2], acc[i][3]));
#pragma unroll
        for (int w = 1; w < 16; w <<= 1) mC = fmaxf(mC, __shfl_xor_sync(0xffffffffu, mC, w));
        float e0 = __expf(acc[i][0] - mC), e1 = __expf(acc[i][1] - mC);
        float e2 = __expf(acc[i][2] - mC), e3 = __expf(acc[i][3] - mC);
        float sC = e0 + e1 + e2 + e3;
#pragma unroll
        for (int w = 1; w < 16; w <<= 1) sC += __shfl_xor_sync(0xffffffffu, sC, w);

        float m2 = fmaxf(fmaxf(acc[i][4], acc[i][5]), fmaxf(acc[i][6], acc[i][7]));
#pragma unroll
        for (int w = 1; w < 8; w <<= 1) m2 = fmaxf(m2, __shfl_xor_sync(0xffffffffu, m2, w));
        float f0 = __expf(acc[i][4] - m2), f1 = __expf(acc[i][5] - m2);
        float f2 = __expf(acc[i][6] - m2), f3 = __expf(acc[i][7] - m2);
        float s2 = f0 + f1 + f2 + f3;
#pragma unroll
        for (int w = 1; w < 8; w <<= 1) s2 += __shfl_xor_sync(0xffffffffu, s2, w);

        float ip = imp[bs];
        float iC = ip / sC, i2 = ip / s2;
        float4 o0 = {e0 * iC, e1 * iC, e2 * iC, e3 * iC};
        float4 o1 = {f0 * i2, f1 * i2, f2 * i2, f3 * i2};
        *(float4*)&g_prefw[(size_t)bs * NW + tx * 4]      = o0;
        *(float4*)&g_prefw[(size_t)bs * NW + 64 + tx * 4] = o1;
    }
}

// ---------------- stage-1 reduction over S ----------------
__global__ void reduce1_kernel() {
    int b = blockIdx.x, chunk = blockIdx.y, t = threadIdx.x;
    const float* p = g_prefw + ((size_t)b * SEQ + chunk * 64) * NW + t;
    float s = 0.f;
#pragma unroll 8
    for (int i = 0; i < 64; i++) s += p[(size_t)i * NW];
    g_part[(b * 16 + chunk) * NW + t] = s;
}

// ---------------- fused stage-2 reduction + top-k + renormalize ----------------
__device__ void topk_store(const float* v, int n, int k, int* oidx, float* oval) {
    float tmp[64];
    for (int i = 0; i < n; i++) tmp[i] = v[i];
    float sum = 0.f;
    for (int j = 0; j < k; j++) {
        int bi = 0; float bv = tmp[0];
        for (int i = 1; i < n; i++) { if (tmp[i] > bv) { bv = tmp[i]; bi = i; } }
        oidx[j] = bi; oval[j] = bv; sum += bv;
        tmp[bi] = -1e30f;
    }
    float inv = 1.f / (sum + 1e-8f);
    for (int j = 0; j < k; j++) oval[j] *= inv;
}
__global__ void reduce2_topk_kernel() {
    __shared__ float acc[NW];
    int b = blockIdx.x, t = threadIdx.x;
    float s = 0.f;
#pragma unroll
    for (int c = 0; c < 16; c++) s += g_part[(b * 16 + c) * NW + t];
    acc[t] = s;
    __syncthreads();
    if (t == 0)      topk_store(acc,            NC,  KC,  g_cidx + b * KC,  g_cval + b * KC);
    else if (t == 1) topk_store(acc + NC,       NQK, KQK, g_qidx + b * KQK, g_qval + b * KQK);
    else if (t == 2) topk_store(acc + NC + NQK, NV,  KV,  g_vidx + b * KV,  g_vval + b * KV);
}

// ---------------- merged sparse weighted mixes (one kernel, measured good) ----------------
__global__ void build_mix_kernel(const float* __restrict__ CN,
                                 const float* __restrict__ EQK,
                                 const float* __restrict__ EV) {
    const int SZ = DM * RK;
    int b = blockIdx.y;
    int i = blockIdx.x * blockDim.x + threadIdx.x;   // 0 .. 3*SZ-1
    if (i < SZ) {
        float s = 0.f;
#pragma unroll
        for (int j = 0; j < KC; j++) {
            int n = g_cidx[b * KC + j];
            s = fmaf(g_cval[b * KC + j], CN[(size_t)n * SZ + i], s);
        }
        g_sc[(size_t)b * SZ + i] = s;
    } else if (i < 2 * SZ) {
        int p = i - SZ;
        float s = 0.f;
#pragma unroll
        for (int j = 0; j < KQK; j++) {
            int n = g_qidx[b * KQK + j];
            s = fmaf(g_qval[b * KQK + j], EQK[(size_t)n * SZ + p], s);
        }
        g_eqk[(size_t)b * SZ + p] = s;
    } else {
        int p = i - 2 * SZ;
        float s = 0.f;
#pragma unroll
        for (int j = 0; j < KV; j++) {
            int n = g_vidx[b * KV + j];
            s = fmaf(g_vval[b * KV + j], EV[(size_t)n * SZ + p], s);
        }
        g_ev[(size_t)b * SZ + p] = s;
    }
}

// =====================================================================
// tf32 GEMM (nn), double-buffered smem, single sync per k-iter.
// =====================================================================
__global__ __launch_bounds__(256, 2) void gemm_nn_mma(
    const float* __restrict__ A, const float* __restrict__ B,
    float* __restrict__ C, int N, int K,
    long long sA, long long sB, long long sC)
{
    __shared__ uint32_t As[2][128 * 20];
    __shared__ uint32_t Bs[2][16 * 136];
    A += (long long)blockIdx.z * sA;
    B += (long long)blockIdx.z * sB;
    C += (long long)blockIdx.z * sC;
    int tid = threadIdx.x, lane = tid & 31, w = tid >> 5;
    int gq = lane >> 2, qd = lane & 3;
    int wm = w & 3, wn = w >> 2;
    int m0 = blockIdx.y * 128, n0 = blockIdx.x * 128;

    float4 acc[2][8];
#pragma unroll
    for (int i = 0; i < 2; i++)
#pragma unroll
        for (int j = 0; j < 8; j++) acc[i][j] = make_float4(0.f, 0.f, 0.f, 0.f);

    const int nkb = K / 16;
    float4 pa[2], pb[2];

    auto LD = [&](int kb) {
#pragma unroll
        for (int i = 0; i < 2; i++) {
            int f = tid + i * 256; int r = f >> 2, q = f & 3;
            pa[i] = *(const float4*)&A[(size_t)(m0 + r) * K + kb * 16 + q * 4];
        }
#pragma unroll
        for (int i = 0; i < 2; i++) {
            int f = tid + i * 256; int r = f >> 5, c = f & 31;
            pb[i] = *(const float4*)&B[(size_t)(kb * 16 + r) * N + n0 + c * 4];
        }
    };
    auto ST = [&](int buf) {
#pragma unroll
        for (int i = 0; i < 2; i++) {
            int f = tid + i * 256; int r = f >> 2, q = f & 3;
            uint32_t* da = &As[buf][r * 20 + q * 4];
            da[0] = f2tf(pa[i].x); da[1] = f2tf(pa[i].y);
            da[2] = f2tf(pa[i].z); da[3] = f2tf(pa[i].w);
        }
#pragma unroll
        for (int i = 0; i < 2; i++) {
            int f = tid + i * 256; int r = f >> 5, c = f & 31;
            uint32_t* db = &Bs[buf][r * 136 + c * 4];
            db[0] = f2tf(pb[i].x); db[1] = f2tf(pb[i].y);
            db[2] = f2tf(pb[i].z); db[3] = f2tf(pb[i].w);
        }
    };

    LD(0); ST(0); __syncthreads();
    for (int kb = 0; kb < nkb; kb++) {
        bool more = (kb + 1 < nkb);
        if (more) LD(kb + 1);
        int cur = kb & 1;
#pragma unroll
        for (int s = 0; s < 2; s++) {
            int kbs = s * 8;
            uint32_t af[2][4];
#pragma unroll
            for (int i = 0; i < 2; i++) {
                int r = wm * 32 + i * 16 + gq;
                af[i][0] = As[cur][r * 20 + kbs + qd];
                af[i][1] = As[cur][(r + 8) * 20 + kbs + qd];
                af[i][2] = As[cur][r * 20 + kbs + qd + 4];
                af[i][3] = As[cur][(r + 8) * 20 + kbs + qd + 4];
            }
            uint32_t bf[8][2];
#pragma unroll
            for (int j = 0; j < 8; j++) {
                int n = wn * 64 + j * 8 + gq;
                bf[j][0] = Bs[cur][(kbs + qd) * 136 + n];
                bf[j][1] = Bs[cur][(kbs + qd + 4) * 136 + n];
            }
#pragma unroll
            for (int i = 0; i < 2; i++)
#pragma unroll
                for (int j = 0; j < 8; j++)
                    mma_tf32(acc[i][j], af[i], bf[j]);
        }
        if (more) { ST(cur ^ 1); __syncthreads(); }
    }

#pragma unroll
    for (int i = 0; i < 2; i++) {
        int r0 = m0 + wm * 32 + i * 16 + gq;
#pragma unroll
        for (int j = 0; j < 8; j++) {
            int c0 = n0 + wn * 64 + j * 8 + 2 * qd;
            *(float2*)&C[(size_t)r0 * N + c0]       = make_float2(acc[i][j].x, acc[i][j].y);
            *(float2*)&C[(size_t)(r0 + 8) * N + c0] = make_float2(acc[i][j].z, acc[i][j].w);
        }
    }
}

// =====================================================================
// Out-projection (nt), double-buffered smem, single sync per k-iter.
// =====================================================================
__global__ __launch_bounds__(256, 2) void gemm_nt_mma(
    const float* __restrict__ A, const float* __restrict__ B,
    float* __restrict__ C, int N, int K)
{
    __shared__ uint32_t As[2][128 * 20];
    __shared__ uint32_t Bs[2][128 * 20];
    int tid = threadIdx.x, lane = tid & 31, w = tid >> 5;
    int gq = lane >> 2, qd = lane & 3;
    int wm = w & 3, wn = w >> 2;
    int m0 = blockIdx.y * 128, n0 = blockIdx.x * 128;

    float4 acc[2][8];
#pragma unroll
    for (int i = 0; i < 2; i++)
#pragma unroll
        for (int j = 0; j < 8; j++) acc[i][j] = make_float4(0.f, 0.f, 0.f, 0.f);

    const int nkb = K / 16;
    float4 pa[2], pb[2];

    auto LD = [&](int kb) {
#pragma unroll
        for (int i = 0; i < 2; i++) {
            int f = tid + i * 256; int r = f >> 2, q = f & 3;
            pa[i] = *(const float4*)&A[(size_t)(m0 + r) * K + kb * 16 + q * 4];
            pb[i] = *(const float4*)&B[(size_t)(n0 + r) * K + kb * 16 + q * 4];
        }
    };
    auto ST = [&](int buf) {
#pragma unroll
        for (int i = 0; i < 2; i++) {
            int f = tid + i * 256; int r = f >> 2, q = f & 3;
            uint32_t* da = &As[buf][r * 20 + q * 4];
            da[0] = f2tf(pa[i].x); da[1] = f2tf(pa[i].y);
            da[2] = f2tf(pa[i].z); da[3] = f2tf(pa[i].w);
            uint32_t* db = &Bs[buf][r * 20 + q * 4];
            db[0] = f2tf(pb[i].x); db[1] = f2tf(pb[i].y);
            db[2] = f2tf(pb[i].z); db[3] = f2tf(pb[i].w);
        }
    };

    LD(0); ST(0); __syncthreads();
    for (int kb = 0; kb < nkb; kb++) {
        bool more = (kb + 1 < nkb);
        if (more) LD(kb + 1);
        int cur = kb & 1;
#pragma unroll
        for (int s = 0; s < 2; s++) {
            int kbs = s * 8;
            uint32_t af[2][4];
#pragma unroll
            for (int i = 0; i < 2; i++) {
                int r = wm * 32 + i * 16 + gq;
                af[i][0] = As[cur][r * 20 + kbs + qd];
                af[i][1] = As[cur][(r + 8) * 20 + kbs + qd];
                af[i][2] = As[cur][r * 20 + kbs + qd + 4];
                af[i][3] = As[cur][(r + 8) * 20 + kbs + qd + 4];
            }
            uint32_t bf[8][2];
#pragma unroll
            for (int j = 0; j < 8; j++) {
                int n = wn * 64 + j * 8 + gq;
                bf[j][0] = Bs[cur][n * 20 + kbs + qd];
                bf[j][1] = Bs[cur][n * 20 + kbs + qd + 4];
            }
#pragma unroll
            for (int i = 0; i < 2; i++)
#pragma unroll
                for (int j = 0; j < 8; j++)
                    mma_tf32(acc[i][j], af[i], bf[j]);
        }
        if (more) { ST(cur ^ 1); __syncthreads(); }
    }

#pragma unroll
    for (int i = 0; i < 2; i++) {
        int r0 = m0 + wm * 32 + i * 16 + gq;
#pragma unroll
        for (int j = 0; j < 8; j++) {
            int c0 = n0 + wn * 64 + j * 8 + 2 * qd;
            *(float2*)&C[(size_t)r0 * N + c0]       = make_float2(acc[i][j].x, acc[i][j].y);
            *(float2*)&C[(size_t)(r0 + 8) * N + c0] = make_float2(acc[i][j].z, acc[i][j].w);
        }
    }
}

// =====================================================================
// Flash attention (K==Q), causal, tf32 mma — round-5 known-good:
// 64-row q-tiles, 4 warps, 128 threads (3 CTAs/SM residency).
// =====================================================================
__global__ __launch_bounds__(128) void flash_mma() {
    extern __shared__ uint32_t sm[];
    uint32_t* Qs = sm;                 // 64 x 68 (reused for P)
    uint32_t* Ks = sm + 64 * 68;
    uint32_t* Vs = sm + 2 * 64 * 68;   // 64 x 72

    int qt = gridDim.x - 1 - blockIdx.x;
    int h = blockIdx.y, b = blockIdx.z;
    int tid = threadIdx.x, lane = tid & 31, w = tid >> 5;
    int gq = lane >> 2, qd = lane & 3;

    const float* Qb = g_Q + (size_t)b * SEQ * DM + (size_t)h * DH;
    const float* Vb = g_V + (size_t)b * SEQ * DM + (size_t)h * DH;

    for (int f = tid; f < 64 * 16; f += 128) {
        int r = f >> 4, q = f & 15;
        float4 v = *(const float4*)&Qb[(size_t)(qt * 64 + r) * DM + q * 4];
        uint32_t* d = &Qs[r * 68 + q * 4];
        d[0] = f2tf(v.x); d[1] = f2tf(v.y); d[2] = f2tf(v.z); d[3] = f2tf(v.w);
    }
    __syncthreads();

    uint32_t qa[8][4];
    int qr = w * 16 + gq;
#pragma unroll
    for (int ka = 0; ka < 8; ka++) {
        qa[ka][0] = Qs[qr * 68 + ka * 8 + qd];
        qa[ka][1] = Qs[(qr + 8) * 68 + ka * 8 + qd];
        qa[ka][2] = Qs[qr * 68 + ka * 8 + qd + 4];
        qa[ka][3] = Qs[(qr + 8) * 68 + ka * 8 + qd + 4];
    }

    float mr0 = -1e30f, mr1 = -1e30f, lr0 = 0.f, lr1 = 0.f;
    float4 oacc[8];
#pragma unroll
    for (int j = 0; j < 8; j++) oacc[j] = make_float4(0.f, 0.f, 0.f, 0.f);

    int row0 = qt * 64 + w * 16 + gq;
    int row1 = row0 + 8;
    const float scale = 0.125f;

    for (int kt = 0; kt <= qt; kt++) {
        __syncthreads();
        for (int f = tid; f < 64 * 16; f += 128) {
            int r = f >> 4, q = f & 15;
            float4 kv = *(const float4*)&Qb[(size_t)(kt * 64 + r) * DM + q * 4];
            uint32_t* dk = &Ks[r * 68 + q * 4];
            dk[0] = f2tf(kv.x); dk[1] = f2tf(kv.y); dk[2] = f2tf(kv.z); dk[3] = f2tf(kv.w);
            float4 vv = *(const float4*)&Vb[(size_t)(kt * 64 + r) * DM + q * 4];
            uint32_t* dv = &Vs[r * 72 + q * 4];
            dv[0] = f2tf(vv.x); dv[1] = f2tf(vv.y); dv[2] = f2tf(vv.z); dv[3] = f2tf(vv.w);
        }
        __syncthreads();

        float4 sacc[8];
#pragma unroll
        for (int j = 0; j < 8; j++) sacc[j] = make_float4(0.f, 0.f, 0.f, 0.f);
#pragma unroll
        for (int ka = 0; ka < 8; ka++) {
#pragma unroll
            for (int j = 0; j < 8; j++) {
                uint32_t bb[2];
                bb[0] = Ks[(j * 8 + gq) * 68 + ka * 8 + qd];
                bb[1] = Ks[(j * 8 + gq) * 68 + ka * 8 + qd + 4];
                mma_tf32(sacc[j], qa[ka], bb);
            }
        }

        bool diag = (kt == qt);
        float p0[8], p1[8], p2[8], p3[8];
        float mx0 = -1e30f, mx1 = -1e30f;
#pragma unroll
        for (int j = 0; j < 8; j++) {
            int col = kt * 64 + j * 8 + 2 * qd;
            float c0 = sacc[j].x * scale, c1 = sacc[j].y * scale;
            float c2 = sacc[j].z * scale, c3 = sacc[j].w * scale;
            if (diag) {
                if (col     > row0) c0 = -1e30f;
                if (col + 1 > row0) c1 = -1e30f;
                if (col     > row1) c2 = -1e30f;
                if (col + 1 > row1) c3 = -1e30f;
            }
            p0[j] = c0; p1[j] = c1; p2[j] = c2; p3[j] = c3;
            mx0 = fmaxf(mx0, fmaxf(c0, c1));
            mx1 = fmaxf(mx1, fmaxf(c2, c3));
        }
        mx0 = fmaxf(mx0, __shfl_xor_sync(0xffffffffu, mx0, 1));
        mx0 = fmaxf(mx0, __shfl_xor_sync(0xffffffffu, mx0, 2));
        mx1 = fmaxf(mx1, __shfl_xor_sync(0xffffffffu, mx1, 1));
        mx1 = fmaxf(mx1, __shfl_xor_sync(0xffffffffu, mx1, 2));

        float mn0 = fmaxf(mr0, mx0), mn1 = fmaxf(mr1, mx1);
        float al0 = __expf(mr0 - mn0), al1 = __expf(mr1 - mn1);
        float ps0 = 0.f, ps1 = 0.f;
#pragma unroll
        for (int j = 0; j < 8; j++) {
            p0[j] = __expf(p0[j] - mn0); p1[j] = __expf(p1[j] - mn0);
            p2[j] = __expf(p2[j] - mn1); p3[j] = __expf(p3[j] - mn1);
            ps0 += p0[j] + p1[j];
            ps1 += p2[j] + p3[j];
        }
        ps0 += __shfl_xor_sync(0xffffffffu, ps0, 1);
        ps0 += __shfl_xor_sync(0xffffffffu, ps0, 2);
        ps1 += __shfl_xor_sync(0xffffffffu, ps1, 1);
        ps1 += __shfl_xor_sync(0xffffffffu, ps1, 2);

        lr0 = lr0 * al0 + ps0; lr1 = lr1 * al1 + ps1;
        mr0 = mn0; mr1 = mn1;
#pragma unroll
        for (int j = 0; j < 8; j++) {
            oacc[j].x *= al0; oacc[j].y *= al0;
            oacc[j].z *= al1; oacc[j].w *= al1;
        }

        int pr0 = w * 16 + gq;
#pragma unroll
        for (int j = 0; j < 8; j++) {
            int cl = j * 8 + 2 * qd;
            Qs[pr0 * 68 + cl]           = f2tf(p0[j]);
            Qs[pr0 * 68 + cl + 1]       = f2tf(p1[j]);
            Qs[(pr0 + 8) * 68 + cl]     = f2tf(p2[j]);
            Qs[(pr0 + 8) * 68 + cl + 1] = f2tf(p3[j]);
        }
        __syncwarp();

#pragma unroll
        for (int ka = 0; ka < 8; ka++) {
            uint32_t pa[4];
            pa[0] = Qs[pr0 * 68 + ka * 8 + qd];
            pa[1] = Qs[(pr0 + 8) * 68 + ka * 8 + qd];
            pa[2] = Qs[pr0 * 68 + ka * 8 + qd + 4];
            pa[3] = Qs[(pr0 + 8) * 68 + ka * 8 + qd + 4];
#pragma unroll
            for (int j = 0; j < 8; j++) {
                uint32_t vb[2];
                vb[0] = Vs[(ka * 8 + qd) * 72 + j * 8 + gq];
                vb[1] = Vs[(ka * 8 + qd + 4) * 72 + j * 8 + gq];
                mma_tf32(oacc[j], pa, vb);
            }
        }
    }

    float inv0 = 1.f / lr0, inv1 = 1.f / lr1;
    float* Ob = g_ao + ((size_t)b * SEQ + row0) * DM + (size_t)h * DH;
#pragma unroll
    for (int j = 0; j < 8; j++) {
        int c = j * 8 + 2 * qd;
        *(float2*)&Ob[c]            = make_float2(oacc[j].x * inv0, oacc[j].y * inv0);
        *(float2*)&Ob[8 * DM + c]   = make_float2(oacc[j].z * inv1, oacc[j].w * inv1);
    }
}

// ---------------- launch ----------------
extern "C" void kernel_launch(void* const* d_in, const int* in_sizes, int n_in,
                              void* d_out, int out_size) {
    const float* x   = (const float*)d_in[0];
    const float* imp = (const float*)d_in[1];
    const float* Wc  = (const float*)d_in[2];
    const float* Wqk = (const float*)d_in[3];
    const float* Wv  = (const float*)d_in[4];
    const float* CN  = (const float*)d_in[5];
    const float* EQK = (const float*)d_in[6];
    const float* EV  = (const float*)d_in[7];
    const float* Wo  = (const float*)d_in[8];
    float* out = (float*)d_out;

    float *p_sc, *p_eqk, *p_ev, *p_h, *p_Q, *p_V, *p_ao;
    cudaGetSymbolAddress((void**)&p_sc,  g_sc);
    cudaGetSymbolAddress((void**)&p_eqk, g_eqk);
    cudaGetSymbolAddress((void**)&p_ev,  g_ev);
    cudaGetSymbolAddress((void**)&p_h,   g_h);
    cudaGetSymbolAddress((void**)&p_Q,   g_Q);
    cudaGetSymbolAddress((void**)&p_V,   g_V);
    cudaGetSymbolAddress((void**)&p_ao,  g_ao);

    static int smem_set = 0;
    const int flash_smem = (64 * 68 + 64 * 68 + 64 * 72) * (int)sizeof(uint32_t); // 53248
    if (!smem_set) {
        cudaFuncSetAttribute(flash_mma,
                             cudaFuncAttributeMaxDynamicSharedMemorySize, flash_smem);
        smem_set = 1;
    }

    // 1) router GEMM + fused softmax*importance (BM=128, round-5)
    router_gemm<<<dim3(1, (BATCH * SEQ) / 128), 256>>>(x, Wc, Wqk, Wv, imp);
    // 2) reduction over S + top-k (fused)
    reduce1_kernel<<<dim3(BATCH, 16), NW>>>();
    reduce2_topk_kernel<<<BATCH, NW>>>();
    // 3) merged sparse mixes
    build_mix_kernel<<<dim3(3 * (DM * RK) / 256, BATCH), 256>>>(CN, EQK, EV);
    // 4) h = x @ sc (tf32, double-buffered)
    gemm_nn_mma<<<dim3(1, SEQ / 128, BATCH), 256>>>(
        x, p_sc, p_h, RK, DM,
        (long long)SEQ * DM, (long long)DM * RK, (long long)SEQ * RK);
    // 5) Q = h @ eqk (tf32, double-buffered)
    gemm_nn_mma<<<dim3(DM / 128, SEQ / 128, BATCH), 256>>>(
        p_h, p_eqk, p_Q, DM, RK,
        (long long)SEQ * RK, (long long)RK * DM, (long long)SEQ * DM);
    // 6) V = h @ ev (tf32, double-buffered)
    gemm_nn_mma<<<dim3(DM / 128, SEQ / 128, BATCH), 256>>>(
        p_h, p_ev, p_V, DM, RK,
        (long long)SEQ * RK, (long long)RK * DM, (long long)SEQ * DM);
    // 7) flash attention (tf32 mma, 64-row q-tiles — round-5)
    flash_mma<<<dim3(SEQ / 64, NHEAD, BATCH), 128, flash_smem>>>();
    // 8) out = ao @ Wo^T (tf32 mma, double-buffered)
    gemm_nt_mma<<<dim3(DM / 128, (BATCH * SEQ) / 128), 256>>>(
        p_ao, Wo, out, DM, DM);
}